// round 10
// baseline (speedup 1.0000x reference)
#include <cuda_runtime.h>
#include <cstdint>
#include <cstddef>

// Attend_62534723830373: out = softmax(causal(K V^T / sqrt(128))) @ V  (q unused)
// [2,16,2048,128] fp32. tf32 mma.sync flash attention == R9 math/layout, plus:
//  - manual double-buffered operand fragments in both GEMM kt-loops
//  - periodic-4 swizzle-remainder tables (frees ~20 regs for the buffers)
//  - exp2f softmax with log2(e) folded into K's scale.

namespace {

constexpr int S  = 2048;
constexpr int D  = 128;
constexpr int BM = 64;
constexpr int BN = 64;
constexpr int NTHREADS = 128;
constexpr float SCALE2 = 0.08838834764831845f * 1.4426950408889634f;  // /sqrt(128) * log2(e)

constexpr int SK_OFF = 0;                   // K' 64 x 512B   32KB
constexpr int SV_OFF = SK_OFF + 64 * 512;   // V 2 x 64 x 512B 64KB
constexpr int VBYTES = 64 * 512;
constexpr int SP_OFF = SV_OFF + 2 * VBYTES; // P 64 x 256B    16KB
constexpr int SMEM_BYTES = SP_OFF + 64 * 256;   // 114688 -> 2 CTAs/SM

__device__ __forceinline__ uint32_t smem_u32(const void* p) {
    uint32_t a;
    asm("{ .reg .u64 t; cvta.to.shared.u64 t, %1; cvt.u32.u64 %0, t; }" : "=r"(a) : "l"(p));
    return a;
}
__device__ __forceinline__ uint32_t f2tf32(float f) {
    uint32_t u; asm("cvt.rna.tf32.f32 %0, %1;" : "=r"(u) : "f"(f)); return u;
}
__device__ __forceinline__ uint32_t swz(uint32_t row, uint32_t cb, uint32_t rowb) {
    uint32_t block = cb >> 7, rem = cb & 127;
    uint32_t chunk = rem >> 4, inner = rem & 15;
    return row * rowb + block * 128 + (((chunk ^ (row & 7)) << 4) | inner);
}
__device__ __forceinline__ void ldsm4(uint32_t r[4], uint32_t a) {
    asm volatile("ldmatrix.sync.aligned.m8n8.x4.shared.b16 {%0,%1,%2,%3}, [%4];"
                 : "=r"(r[0]), "=r"(r[1]), "=r"(r[2]), "=r"(r[3]) : "r"(a));
}
__device__ __forceinline__ uint32_t lds32(uint32_t a) {
    uint32_t v;
    asm volatile("ld.shared.b32 %0, [%1];" : "=r"(v) : "r"(a));
    return v;
}
__device__ __forceinline__ void sts32(uint32_t a, uint32_t v) {
    asm volatile("st.shared.b32 [%0], %1;" :: "r"(a), "r"(v));
}
__device__ __forceinline__ void cpasync16(uint32_t dst, const void* src) {
    asm volatile("cp.async.cg.shared.global [%0], [%1], 16;" :: "r"(dst), "l"(src) : "memory");
}
__device__ __forceinline__ void cpasync_commit() {
    asm volatile("cp.async.commit_group;" ::: "memory");
}
__device__ __forceinline__ void cpasync_wait0() {
    asm volatile("cp.async.wait_group 0;" ::: "memory");
}
__device__ __forceinline__ void mma8(float* c,
                                     uint32_t a0, uint32_t a1, uint32_t a2, uint32_t a3,
                                     uint32_t b0, uint32_t b1) {
    asm volatile(
        "mma.sync.aligned.m16n8k8.row.col.f32.tf32.tf32.f32 "
        "{%0,%1,%2,%3}, {%4,%5,%6,%7}, {%8,%9}, {%0,%1,%2,%3};"
        : "+f"(c[0]), "+f"(c[1]), "+f"(c[2]), "+f"(c[3])
        : "r"(a0), "r"(a1), "r"(a2), "r"(a3), "r"(b0), "r"(b1));
}

__global__ __launch_bounds__(NTHREADS)
void fa_swp(const float* __restrict__ Kg, const float* __restrict__ Vg,
            float* __restrict__ Og) {
    extern __shared__ __align__(1024) char smem[];
    const uint32_t sb = smem_u32(smem);
    const int tid  = threadIdx.x;
    const int wid  = tid >> 5;
    const int lane = tid & 31;
    const int g    = lane >> 2;
    const int tg   = lane & 3;

    const int bh = blockIdx.y;
    const int qb = (int)gridDim.x - 1 - (int)blockIdx.x;

    const float* Kh = Kg + (size_t)bh * S * D;
    const float* Vh = Vg + (size_t)bh * S * D;
    float*       Oh = Og + (size_t)bh * S * D;

    const int rj = (wid >> 1) * 32;   // GEMM1 j half
    const int ri = (wid & 1) * 32;    // i half
    const int dn = (wid >> 1) * 64;   // GEMM2 d half

    const int mat = lane >> 3, rr = lane & 7;
    const uint32_t rowA = (uint32_t)(((mat & 1) << 3) + rr);
    const uint32_t cbA  = (uint32_t)((mat >> 1) << 4);
    const uint32_t rowB = (uint32_t)(((mat >> 1) << 3) + rr);
    const uint32_t cbB  = (uint32_t)((mat & 1) << 4);

    const int vr = tid & 63;
    const int vc = tid >> 6;

    // ---- periodic-4 swizzle remainder tables (per-lane constants) ----
    uint32_t swA[4], swB[4];
    #pragma unroll
    for (int r = 0; r < 4; ++r) {
        swA[r] = swz(rowA, (uint32_t)r * 32 + cbA, 512) - rowA * 512;
        swB[r] = swz(rowB, (uint32_t)r * 32 + cbB, 512) - rowB * 512;
    }
    // GEMM1 row bases
    const uint32_t vaC0 = (uint32_t)(rj +      rowA) * 512;
    const uint32_t vaC1 = (uint32_t)(rj + 16 + rowA) * 512;
    const uint32_t kb0  = sb + SK_OFF + (uint32_t)(ri +      rowB) * 512;
    const uint32_t kb1  = sb + SK_OFF + (uint32_t)(ri + 16 + rowB) * 512;
    // GEMM2 A (P, 256B rows) bases; kt remainder shared with swA
    const uint32_t pa0 = sb + SP_OFF + (uint32_t)(ri +      rowA) * 256;
    const uint32_t pa1 = sb + SP_OFF + (uint32_t)(ri + 16 + rowA) * 256;
    // GEMM2 B column terms, periodic-4 in nt: cB(nt) = cbt[nt&3] + (nt>>2)*128
    uint32_t cbt0[4], cbt1[4];
    #pragma unroll
    for (int r = 0; r < 4; ++r) {
        const uint32_t dd = (uint32_t)(dn + r * 8 + g) * 4;
        cbt0[r] = swz((uint32_t)tg,     dd, 512);
        cbt1[r] = swz((uint32_t)tg + 4, dd, 512);
    }
    // P store bases
    uint32_t ps[2][4];
    #pragma unroll
    for (int mt = 0; mt < 2; ++mt) {
        const uint32_t jl0 = (uint32_t)(rj + mt * 16 + g) * 4;
        const uint32_t jl1 = jl0 + 32;
        ps[mt][0] = sb + SP_OFF + swz((uint32_t)(ri + 2 * tg),     jl0, 256);
        ps[mt][1] = sb + SP_OFF + swz((uint32_t)(ri + 2 * tg + 1), jl0, 256);
        ps[mt][2] = sb + SP_OFF + swz((uint32_t)(ri + 2 * tg),     jl1, 256);
        ps[mt][3] = sb + SP_OFF + swz((uint32_t)(ri + 2 * tg + 1), jl1, 256);
    }
    // V prefetch destination: base + (q>>3)*128(imm) + dq[q&7]
    uint32_t dq[8];
    #pragma unroll
    for (int r = 0; r < 8; ++r)
        dq[r] = (uint32_t)((r ^ (vr & 7)) << 4);
    const uint32_t vdstBase = (uint32_t)vr * 512 + (uint32_t)vc * 256;

    // ---- prefetch V tile 0 ----
    {
        const char* src = reinterpret_cast<const char*>(Vh + (size_t)vr * D + vc * 64);
        const uint32_t dbase = sb + SV_OFF + vdstBase;
        #pragma unroll
        for (int q = 0; q < 16; ++q)
            cpasync16(dbase + (uint32_t)((q >> 3) * 128) + dq[q & 7], src + q * 16);
        cpasync_commit();
    }

    // ---- load K' tile once (scale*log2e folded, rna tf32) ----
    {
        const float4* src = reinterpret_cast<const float4*>(
            Kh + (size_t)(qb * BM + vr) * D + vc * 64);
        const uint32_t dbase = sb + SK_OFF + vdstBase;
        #pragma unroll
        for (int q = 0; q < 16; ++q) {
            float4 x = src[q];
            uint4 u;
            u.x = f2tf32(x.x * SCALE2); u.y = f2tf32(x.y * SCALE2);
            u.z = f2tf32(x.z * SCALE2); u.w = f2tf32(x.w * SCALE2);
            *reinterpret_cast<uint4*>(smem + (dbase - sb) +
                (uint32_t)((q >> 3) * 128) + dq[q & 7]) = u;
        }
    }

    float oacc[2][8][4];
    #pragma unroll
    for (int mt = 0; mt < 2; ++mt)
        #pragma unroll
        for (int nt = 0; nt < 8; ++nt) {
            oacc[mt][nt][0] = 0.f; oacc[mt][nt][1] = 0.f;
            oacc[mt][nt][2] = 0.f; oacc[mt][nt][3] = 0.f;
        }
    float lsum[4][2];
    #pragma unroll
    for (int nt = 0; nt < 4; ++nt) { lsum[nt][0] = 0.f; lsum[nt][1] = 0.f; }

    const char* gv = reinterpret_cast<const char*>(Vh + (size_t)(BN + vr) * D + vc * 64);

    cpasync_wait0();
    __syncthreads();

    for (int jb = 0; jb <= qb; ++jb) {
        const int cur = jb & 1;
        const uint32_t svc = sb + SV_OFF + (uint32_t)cur * VBYTES;

        // ---- prefetch V(jb+1) ----
        if (jb < qb) {
            const uint32_t dbase = sb + SV_OFF + (uint32_t)(cur ^ 1) * VBYTES + vdstBase;
            #pragma unroll
            for (int q = 0; q < 16; ++q)
                cpasync16(dbase + (uint32_t)((q >> 3) * 128) + dq[q & 7], gv + q * 16);
            cpasync_commit();
            gv += (size_t)BN * D * 4;
        }

        // ---- GEMM1: S^T[32j x 32i] = V * K'^T  (double-buffered fragments) ----
        const uint32_t va0 = svc + vaC0;
        const uint32_t va1 = svc + vaC1;
        float sacc[2][4][4];
        #pragma unroll
        for (int mt = 0; mt < 2; ++mt)
            #pragma unroll
            for (int nt = 0; nt < 4; ++nt) {
                sacc[mt][nt][0] = 0.f; sacc[mt][nt][1] = 0.f;
                sacc[mt][nt][2] = 0.f; sacc[mt][nt][3] = 0.f;
            }
        {
            uint32_t af[2][2][4], bf[2][2][4];
            ldsm4(af[0][0], va0 + swA[0]);
            ldsm4(af[0][1], va1 + swA[0]);
            ldsm4(bf[0][0], kb0 + swB[0]);
            ldsm4(bf[0][1], kb1 + swB[0]);
            #pragma unroll
            for (int kt = 0; kt < 16; ++kt) {
                const int cb = kt & 1, nb = cb ^ 1;
                if (kt < 15) {
                    const uint32_t blk = (uint32_t)(((kt + 1) >> 2) * 128);
                    const uint32_t oA = swA[(kt + 1) & 3] + blk;
                    const uint32_t oB = swB[(kt + 1) & 3] + blk;
                    ldsm4(af[nb][0], va0 + oA);
                    ldsm4(af[nb][1], va1 + oA);
                    ldsm4(bf[nb][0], kb0 + oB);
                    ldsm4(bf[nb][1], kb1 + oB);
                }
                #pragma unroll
                for (int mt = 0; mt < 2; ++mt)
                    #pragma unroll
                    for (int np = 0; np < 2; ++np) {
                        mma8(sacc[mt][2 * np],     af[cb][mt][0], af[cb][mt][1],
                             af[cb][mt][2], af[cb][mt][3], bf[cb][np][0], bf[cb][np][1]);
                        mma8(sacc[mt][2 * np + 1], af[cb][mt][0], af[cb][mt][1],
                             af[cb][mt][2], af[cb][mt][3], bf[cb][np][2], bf[cb][np][3]);
                    }
            }
        }

        // ---- softmax: mask, exp2, lsum, store P transposed ----
        #pragma unroll
        for (int mt = 0; mt < 2; ++mt) {
            const int j0 = jb * BN + rj + mt * 16 + g;
            const int j1 = j0 + 8;
            #pragma unroll
            for (int nt = 0; nt < 4; ++nt) {
                const int i0 = qb * BM + ri + nt * 8 + 2 * tg;
                float p00 = (j0 <= i0)     ? exp2f(sacc[mt][nt][0]) : 0.f;
                float p01 = (j0 <= i0 + 1) ? exp2f(sacc[mt][nt][1]) : 0.f;
                float p10 = (j1 <= i0)     ? exp2f(sacc[mt][nt][2]) : 0.f;
                float p11 = (j1 <= i0 + 1) ? exp2f(sacc[mt][nt][3]) : 0.f;
                lsum[nt][0] += p00 + p10;
                lsum[nt][1] += p01 + p11;
                const uint32_t off = (uint32_t)nt * 2048;
                sts32(ps[mt][0] + off, f2tf32(p00));
                sts32(ps[mt][1] + off, f2tf32(p01));
                sts32(ps[mt][2] + off, f2tf32(p10));
                sts32(ps[mt][3] + off, f2tf32(p11));
            }
        }
        __syncthreads();   // P visible

        // ---- GEMM2: O[32i x 64d] += P * V  (double-buffered A and B) ----
        {
            uint32_t ap[2][2][4], bv[2][8][2];
            ldsm4(ap[0][0], pa0 + swA[0]);
            ldsm4(ap[0][1], pa1 + swA[0]);
            #pragma unroll
            for (int nt = 0; nt < 8; ++nt) {
                const uint32_t blkn = (uint32_t)((nt >> 2) * 128);
                bv[0][nt][0] = lds32(svc + cbt0[nt & 3] + blkn);
                bv[0][nt][1] = lds32(svc + cbt1[nt & 3] + blkn);
            }
            #pragma unroll
            for (int kt = 0; kt < 8; ++kt) {
                const int cb = kt & 1, nb = cb ^ 1;
                if (kt < 7) {
                    const uint32_t blk = (uint32_t)(((kt + 1) >> 2) * 128);
                    const uint32_t oA = swA[(kt + 1) & 3] + blk;
                    ldsm4(ap[nb][0], pa0 + oA);
                    ldsm4(ap[nb][1], pa1 + oA);
                    const uint32_t kadd = svc + (uint32_t)(kt + 1) * 4096;
                    #pragma unroll
                    for (int nt = 0; nt < 8; ++nt) {
                        const uint32_t blkn = (uint32_t)((nt >> 2) * 128);
                        bv[nb][nt][0] = lds32(kadd + cbt0[nt & 3] + blkn);
                        bv[nb][nt][1] = lds32(kadd + cbt1[nt & 3] + blkn);
                    }
                }
                #pragma unroll
                for (int nt = 0; nt < 8; ++nt) {
                    mma8(oacc[0][nt], ap[cb][0][0], ap[cb][0][1], ap[cb][0][2],
                         ap[cb][0][3], bv[cb][nt][0], bv[cb][nt][1]);
                    mma8(oacc[1][nt], ap[cb][1][0], ap[cb][1][1], ap[cb][1][2],
                         ap[cb][1][3], bv[cb][nt][0], bv[cb][nt][1]);
                }
            }
        }

        cpasync_wait0();
        __syncthreads();   // sP/sV[cur] free; next V landed
    }

    // ---- epilogue (same as R9) ----
    #pragma unroll
    for (int nt = 0; nt < 4; ++nt)
        #pragma unroll
        for (int c = 0; c < 2; ++c) {
            float v = lsum[nt][c];
            v += __shfl_xor_sync(0xffffffffu, v, 4);
            v += __shfl_xor_sync(0xffffffffu, v, 8);
            v += __shfl_xor_sync(0xffffffffu, v, 16);
            lsum[nt][c] = v;
        }
    float* lbuf = reinterpret_cast<float*>(smem + SP_OFF);
    if (g == 0) {
        #pragma unroll
        for (int nt = 0; nt < 4; ++nt) {
            lbuf[(wid >> 1) * 64 + ri + nt * 8 + 2 * tg]     = lsum[nt][0];
            lbuf[(wid >> 1) * 64 + ri + nt * 8 + 2 * tg + 1] = lsum[nt][1];
        }
    }
    __syncthreads();

    #pragma unroll
    for (int mt = 0; mt < 2; ++mt) {
        const int il0 = ri + mt * 16 + g;
        const int il1 = il0 + 8;
        const float inv0 = 1.f / (lbuf[il0] + lbuf[64 + il0]);
        const float inv1 = 1.f / (lbuf[il1] + lbuf[64 + il1]);
        float* o0 = Oh + (size_t)(qb * BM + il0) * D + dn + 2 * tg;
        float* o1 = Oh + (size_t)(qb * BM + il1) * D + dn + 2 * tg;
        #pragma unroll
        for (int nt = 0; nt < 8; ++nt) {
            float2 w0 = make_float2(oacc[mt][nt][0] * inv0, oacc[mt][nt][1] * inv0);
            float2 w1 = make_float2(oacc[mt][nt][2] * inv1, oacc[mt][nt][3] * inv1);
            *reinterpret_cast<float2*>(o0 + nt * 8) = w0;
            *reinterpret_cast<float2*>(o1 + nt * 8) = w1;
        }
    }
}

}  // namespace

extern "C" void kernel_launch(void* const* d_in, const int* /*in_sizes*/, int /*n_in*/,
                              void* d_out, int /*out_size*/) {
    // inputs: d_in[0]=q (unused by reference), d_in[1]=k, d_in[2]=v
    const float* k = reinterpret_cast<const float*>(d_in[1]);
    const float* v = reinterpret_cast<const float*>(d_in[2]);
    float* o = reinterpret_cast<float*>(d_out);

    cudaFuncSetAttribute(fa_swp,
                         cudaFuncAttributeMaxDynamicSharedMemorySize, SMEM_BYTES);
    dim3 grid(S / BM, 32);
    fa_swp<<<grid, NTHREADS, SMEM_BYTES>>>(k, v, o);
}

// round 11
// speedup vs baseline: 1.4163x; 1.4163x over previous
#include <cuda_runtime.h>
#include <cuda_fp16.h>
#include <cstdint>
#include <cstddef>

// Attend_62534723830373: out = softmax(causal(K V^T / sqrt(128))) @ V  (q unused)
// [2,16,2048,128] fp32. fp16 mma.sync m16n8k16 (fp32 accum) flash attention.
// K', V, P all fp16 in smem. GEMM1: S^T = V*K'^T (ldsm non-trans both).
// P stored j-major as f16x2; GEMM2 reads A=P and B=V via ldsm.trans.
// No-max softmax (scores bounded). V converted fp32->fp16 by threads,
// double-buffered with LDG batches hidden under the GEMMs.

namespace {

constexpr int S  = 2048;
constexpr int D  = 128;
constexpr int BM = 64;
constexpr int BN = 64;
constexpr int NTHREADS = 128;
constexpr float SCALE_F = 0.08838834764831845f;

// fp16 tiles: 256B rows (128 halves) for K'/V, 128B rows (64 halves) for P.
constexpr int SK_OFF = 0;                    // K' 64 x 256B = 16KB
constexpr int SV_OFF = 16384;                // V 2 x 64 x 256B = 32KB
constexpr int VBYTES = 16384;
constexpr int SP_OFF = SV_OFF + 2 * VBYTES;  // P 64 x 128B = 8KB
constexpr int SMEM_BYTES = SP_OFF + 8192;    // 57344

__device__ __forceinline__ uint32_t smem_u32(const void* p) {
    uint32_t a;
    asm("{ .reg .u64 t; cvta.to.shared.u64 t, %1; cvt.u32.u64 %0, t; }" : "=r"(a) : "l"(p));
    return a;
}
// pack (lo,hi) floats -> f16x2 (lo in low half)
__device__ __forceinline__ uint32_t packh2(float lo, float hi) {
    uint32_t d;
    asm("cvt.rn.f16x2.f32 %0, %1, %2;" : "=r"(d) : "f"(hi), "f"(lo));
    return d;
}
// swizzled byte offset of (row, colbyte) for rowb-byte rows; 16B chunks xor row&7
__device__ __forceinline__ uint32_t swzoff(uint32_t row, uint32_t cb, uint32_t rowb) {
    uint32_t block = cb >> 7, rem = cb & 127;
    uint32_t chunk = rem >> 4, inner = rem & 15;
    return row * rowb + block * 128 + (((chunk ^ (row & 7)) << 4) | inner);
}
__device__ __forceinline__ void ldsm4(uint32_t r[4], uint32_t a) {
    asm volatile("ldmatrix.sync.aligned.m8n8.x4.shared.b16 {%0,%1,%2,%3}, [%4];"
                 : "=r"(r[0]), "=r"(r[1]), "=r"(r[2]), "=r"(r[3]) : "r"(a));
}
__device__ __forceinline__ void ldsm4t(uint32_t r[4], uint32_t a) {
    asm volatile("ldmatrix.sync.aligned.m8n8.x4.trans.shared.b16 {%0,%1,%2,%3}, [%4];"
                 : "=r"(r[0]), "=r"(r[1]), "=r"(r[2]), "=r"(r[3]) : "r"(a));
}
__device__ __forceinline__ void sts32(uint32_t a, uint32_t v) {
    asm volatile("st.shared.b32 [%0], %1;" :: "r"(a), "r"(v));
}
__device__ __forceinline__ void sts128(uint32_t a, uint32_t x, uint32_t y,
                                       uint32_t z, uint32_t w) {
    asm volatile("st.shared.v4.b32 [%0], {%1,%2,%3,%4};"
                 :: "r"(a), "r"(x), "r"(y), "r"(z), "r"(w));
}
// D(16x8,f32) += A(16x16,f16) * B(16x8,f16)
__device__ __forceinline__ void mma16(float* c, const uint32_t a[4],
                                      uint32_t b0, uint32_t b1) {
    asm volatile(
        "mma.sync.aligned.m16n8k16.row.col.f32.f16.f16.f32 "
        "{%0,%1,%2,%3}, {%4,%5,%6,%7}, {%8,%9}, {%0,%1,%2,%3};"
        : "+f"(c[0]), "+f"(c[1]), "+f"(c[2]), "+f"(c[3])
        : "r"(a[0]), "r"(a[1]), "r"(a[2]), "r"(a[3]), "r"(b0), "r"(b1));
}

__global__ __launch_bounds__(NTHREADS)
void fa_h16(const float* __restrict__ Kg, const float* __restrict__ Vg,
            float* __restrict__ Og) {
    extern __shared__ __align__(1024) char smem[];
    const uint32_t sb = smem_u32(smem);
    const int tid  = threadIdx.x;
    const int wid  = tid >> 5;
    const int lane = tid & 31;
    const int g    = lane >> 2;
    const int tg   = lane & 3;
    const int mat  = lane >> 3;
    const int rr   = lane & 7;

    const int bh = blockIdx.y;
    const int qb = (int)gridDim.x - 1 - (int)blockIdx.x;   // longest first

    const float* Kh = Kg + (size_t)bh * S * D;
    const float* Vh = Vg + (size_t)bh * S * D;
    float*       Oh = Og + (size_t)bh * S * D;

    const int rj = (wid >> 1) * 32;   // GEMM1 j half
    const int ri = (wid & 1) * 32;    // i half
    const int dn = (wid >> 1) * 64;   // GEMM2 d half

    // fragment lane-address components
    const uint32_t rowA = (uint32_t)(((mat & 1) << 3) + rr);
    const uint32_t cbA  = (uint32_t)((mat >> 1) << 4);
    const uint32_t rowB = (uint32_t)(((mat >> 1) << 3) + rr);
    const uint32_t cbB  = (uint32_t)((mat & 1) << 4);

    // ---- loop-invariant address tables ----
    uint32_t swA1[4], swB1[4];                 // GEMM1 k-step remainders (256B rows)
    #pragma unroll
    for (int r = 0; r < 4; ++r) {
        swA1[r] = swzoff(rowA, (uint32_t)r * 32 + cbA, 256) - rowA * 256;
        swB1[r] = swzoff(rowB, (uint32_t)r * 32 + cbB, 256) - rowB * 256;
    }
    const uint32_t vaC0 = (uint32_t)(rj +      rowA) * 256;   // + svc
    const uint32_t vaC1 = (uint32_t)(rj + 16 + rowA) * 256;
    const uint32_t kb0  = sb + SK_OFF + (uint32_t)(ri +      rowB) * 256;
    const uint32_t kb1  = sb + SK_OFF + (uint32_t)(ri + 16 + rowB) * 256;
    // GEMM2 A (P j-major, trans): addr = ptb[ih] + kt*2048
    uint32_t ptb[2];
    #pragma unroll
    for (int ih = 0; ih < 2; ++ih)
        ptb[ih] = sb + SP_OFF + swzoff(rowB, (uint32_t)(ri * 2 + ih * 32) + cbB, 128);
    // GEMM2 B (V j-major, trans): addr = svc + rowA*256 + kt*4096 + remVT[dp]
    uint32_t remVT[4];
    #pragma unroll
    for (int dp = 0; dp < 4; ++dp)
        remVT[dp] = swzoff(rowA, (uint32_t)(dn * 2 + dp * 32) + cbA, 256) - rowA * 256;
    // P store: addr = psb[jh][jhalf] + remP(ng)
    const uint32_t ri8 = (uint32_t)(ri >> 3);
    uint32_t psb[2][2];
    #pragma unroll
    for (int jh = 0; jh < 2; ++jh) {
        psb[jh][0] = sb + SP_OFF + (uint32_t)(rj + jh * 16 + g) * 128 + (uint32_t)tg * 4;
        psb[jh][1] = psb[jh][0] + 8 * 128;
    }
    // V/K fp16 conversion-store: thread owns row vr, d-half vh
    const int vr  = tid >> 1;
    const int vh  = tid & 1;
    const uint32_t vrl = (uint32_t)(vr & 7);
    const uint32_t vstBase = (uint32_t)vr * 256 + (uint32_t)vh * 128;

    // ---- prologue: K' (scaled) and V tile 0 to fp16 smem ----
    {
        const float4* ks = reinterpret_cast<const float4*>(
            Kh + (size_t)(qb * BM + vr) * D + vh * 64);
        const float4* vs = reinterpret_cast<const float4*>(
            Vh + (size_t)vr * D + vh * 64);
        #pragma unroll
        for (int q = 0; q < 8; ++q) {
            const uint32_t off = vstBase + (uint32_t)(((uint32_t)q ^ vrl) << 4);
            float4 x0 = ks[2 * q], x1 = ks[2 * q + 1];
            sts128(sb + SK_OFF + off,
                   packh2(x0.x * SCALE_F, x0.y * SCALE_F),
                   packh2(x0.z * SCALE_F, x0.w * SCALE_F),
                   packh2(x1.x * SCALE_F, x1.y * SCALE_F),
                   packh2(x1.z * SCALE_F, x1.w * SCALE_F));
            float4 y0 = vs[2 * q], y1 = vs[2 * q + 1];
            sts128(sb + SV_OFF + off,
                   packh2(y0.x, y0.y), packh2(y0.z, y0.w),
                   packh2(y1.x, y1.y), packh2(y1.z, y1.w));
        }
    }

    float oacc[2][8][4];
    #pragma unroll
    for (int ih = 0; ih < 2; ++ih)
        #pragma unroll
        for (int dg = 0; dg < 8; ++dg) {
            oacc[ih][dg][0] = 0.f; oacc[ih][dg][1] = 0.f;
            oacc[ih][dg][2] = 0.f; oacc[ih][dg][3] = 0.f;
        }
    float lsum[4][2];
    #pragma unroll
    for (int ng = 0; ng < 4; ++ng) { lsum[ng][0] = 0.f; lsum[ng][1] = 0.f; }

    __syncthreads();   // K' + V0 visible

    for (int jb = 0; jb <= qb; ++jb) {
        const int cur = jb & 1;
        const uint32_t svc  = sb + SV_OFF + (uint32_t)cur * VBYTES;
        const uint32_t svn  = sb + SV_OFF + (uint32_t)(cur ^ 1) * VBYTES + vstBase;
        const bool pre = (jb < qb);
        const float4* vs = reinterpret_cast<const float4*>(
            Vh + (size_t)((jb + 1) * BN + vr) * D + vh * 64);

        // batch A of next V (LDG latency hidden by GEMM1)
        float4 vA[8];
        if (pre) {
            #pragma unroll
            for (int q = 0; q < 8; ++q) vA[q] = vs[q];
        }

        // ---- GEMM1: S^T[32j x 32i] = V[32j x 128d] * K'^T ----
        const uint32_t va0 = svc + vaC0;
        const uint32_t va1 = svc + vaC1;
        float sacc[2][4][4];
        #pragma unroll
        for (int jh = 0; jh < 2; ++jh)
            #pragma unroll
            for (int ng = 0; ng < 4; ++ng) {
                sacc[jh][ng][0] = 0.f; sacc[jh][ng][1] = 0.f;
                sacc[jh][ng][2] = 0.f; sacc[jh][ng][3] = 0.f;
            }
        #pragma unroll
        for (int kt = 0; kt < 8; ++kt) {
            const uint32_t offA = swA1[kt & 3] + (uint32_t)((kt >> 2) * 128);
            const uint32_t offB = swB1[kt & 3] + (uint32_t)((kt >> 2) * 128);
            uint32_t a[2][4], b[2][4];
            ldsm4(a[0], va0 + offA);
            ldsm4(a[1], va1 + offA);
            ldsm4(b[0], kb0 + offB);
            ldsm4(b[1], kb1 + offB);
            #pragma unroll
            for (int jh = 0; jh < 2; ++jh)
                #pragma unroll
                for (int ng = 0; ng < 4; ++ng)
                    mma16(sacc[jh][ng], a[jh],
                          b[ng >> 1][(ng & 1) * 2], b[ng >> 1][(ng & 1) * 2 + 1]);
        }

        // convert+store batch A; issue LDG batch B (hidden by softmax+GEMM2)
        float4 vB[8];
        if (pre) {
            #pragma unroll
            for (int q = 0; q < 4; ++q) {
                const uint32_t off = (uint32_t)(((uint32_t)q ^ vrl) << 4);
                sts128(svn + off,
                       packh2(vA[2 * q].x, vA[2 * q].y),
                       packh2(vA[2 * q].z, vA[2 * q].w),
                       packh2(vA[2 * q + 1].x, vA[2 * q + 1].y),
                       packh2(vA[2 * q + 1].z, vA[2 * q + 1].w));
            }
            #pragma unroll
            for (int q = 0; q < 8; ++q) vB[q] = vs[8 + q];
        }

        // ---- softmax: mask, exp, lsum, store P (j-major f16x2) ----
        #pragma unroll
        for (int jh = 0; jh < 2; ++jh) {
            const int j0 = jb * BN + rj + jh * 16 + g;
            const int j1 = j0 + 8;
            #pragma unroll
            for (int ng = 0; ng < 4; ++ng) {
                const int i0 = qb * BM + ri + ng * 8 + 2 * tg;
                float p00 = (j0 <= i0)     ? __expf(sacc[jh][ng][0]) : 0.f;
                float p01 = (j0 <= i0 + 1) ? __expf(sacc[jh][ng][1]) : 0.f;
                float p10 = (j1 <= i0)     ? __expf(sacc[jh][ng][2]) : 0.f;
                float p11 = (j1 <= i0 + 1) ? __expf(sacc[jh][ng][3]) : 0.f;
                lsum[ng][0] += p00 + p10;
                lsum[ng][1] += p01 + p11;
                const uint32_t rem = ((ri8 + (uint32_t)ng) ^ (uint32_t)g) << 4;
                sts32(psb[jh][0] + rem, packh2(p00, p01));
                sts32(psb[jh][1] + rem, packh2(p10, p11));
            }
        }
        __syncthreads();   // P visible

        // ---- GEMM2: O[32i x 64d] += P[32i x 64j] * V[64j x 64d] ----
        const uint32_t vtb = svc + rowA * 256;
        #pragma unroll
        for (int kt = 0; kt < 4; ++kt) {
            uint32_t aP[2][4], bV[4][4];
            ldsm4t(aP[0], ptb[0] + (uint32_t)kt * 2048);
            ldsm4t(aP[1], ptb[1] + (uint32_t)kt * 2048);
            #pragma unroll
            for (int dp = 0; dp < 4; ++dp)
                ldsm4t(bV[dp], vtb + (uint32_t)kt * 4096 + remVT[dp]);
            #pragma unroll
            for (int ih = 0; ih < 2; ++ih)
                #pragma unroll
                for (int dg = 0; dg < 8; ++dg)
                    mma16(oacc[ih][dg], aP[ih],
                          bV[dg >> 1][(dg & 1) * 2], bV[dg >> 1][(dg & 1) * 2 + 1]);
        }

        // convert+store batch B of next V
        if (pre) {
            #pragma unroll
            for (int q = 0; q < 4; ++q) {
                const uint32_t off = (uint32_t)((((uint32_t)q + 4) ^ vrl) << 4);
                sts128(svn + off,
                       packh2(vB[2 * q].x, vB[2 * q].y),
                       packh2(vB[2 * q].z, vB[2 * q].w),
                       packh2(vB[2 * q + 1].x, vB[2 * q + 1].y),
                       packh2(vB[2 * q + 1].z, vB[2 * q + 1].w));
            }
        }
        __syncthreads();   // next V visible; P/sV[cur] free
    }

    // ---- epilogue: reduce lsum over j, then across j-half warps via smem ----
    #pragma unroll
    for (int ng = 0; ng < 4; ++ng)
        #pragma unroll
        for (int c = 0; c < 2; ++c) {
            float v = lsum[ng][c];
            v += __shfl_xor_sync(0xffffffffu, v, 4);
            v += __shfl_xor_sync(0xffffffffu, v, 8);
            v += __shfl_xor_sync(0xffffffffu, v, 16);
            lsum[ng][c] = v;
        }
    float* lbuf = reinterpret_cast<float*>(smem + SP_OFF);   // P area free now
    if (g == 0) {
        #pragma unroll
        for (int ng = 0; ng < 4; ++ng) {
            lbuf[(wid >> 1) * 64 + ri + ng * 8 + 2 * tg]     = lsum[ng][0];
            lbuf[(wid >> 1) * 64 + ri + ng * 8 + 2 * tg + 1] = lsum[ng][1];
        }
    }
    __syncthreads();

    // ---- normalize + store O (warp: rows ri..ri+31, cols dn..dn+63) ----
    #pragma unroll
    for (int ih = 0; ih < 2; ++ih) {
        const int il0 = ri + ih * 16 + g;
        const int il1 = il0 + 8;
        const float inv0 = 1.f / (lbuf[il0] + lbuf[64 + il0]);
        const float inv1 = 1.f / (lbuf[il1] + lbuf[64 + il1]);
        float* o0 = Oh + (size_t)(qb * BM + il0) * D + dn + 2 * tg;
        float* o1 = Oh + (size_t)(qb * BM + il1) * D + dn + 2 * tg;
        #pragma unroll
        for (int dg = 0; dg < 8; ++dg) {
            float2 w0 = make_float2(oacc[ih][dg][0] * inv0, oacc[ih][dg][1] * inv0);
            float2 w1 = make_float2(oacc[ih][dg][2] * inv1, oacc[ih][dg][3] * inv1);
            *reinterpret_cast<float2*>(o0 + dg * 8) = w0;
            *reinterpret_cast<float2*>(o1 + dg * 8) = w1;
        }
    }
}

}  // namespace

extern "C" void kernel_launch(void* const* d_in, const int* /*in_sizes*/, int /*n_in*/,
                              void* d_out, int /*out_size*/) {
    // inputs: d_in[0]=q (unused by reference), d_in[1]=k, d_in[2]=v
    const float* k = reinterpret_cast<const float*>(d_in[1]);
    const float* v = reinterpret_cast<const float*>(d_in[2]);
    float* o = reinterpret_cast<float*>(d_out);

    cudaFuncSetAttribute(fa_h16,
                         cudaFuncAttributeMaxDynamicSharedMemorySize, SMEM_BYTES);
    dim3 grid(S / BM, 32);
    fa_h16<<<grid, NTHREADS, SMEM_BYTES>>>(k, v, o);
}

// round 12
// speedup vs baseline: 1.8167x; 1.2827x over previous
#include <cuda_runtime.h>
#include <cuda_fp16.h>
#include <cstdint>
#include <cstddef>

// Attend_62534723830373: out = softmax(causal(K V^T / sqrt(128))) @ V  (q unused)
// [2,16,2048,128] fp32. fp16 m16n8k16 flash attention (R11 math, bit-identical),
// plus a pre-pass kernel that converts K*scale and V to fp16 ONCE into __device__
// scratch, so the flash kernel streams fp16 tiles via cp.async (no per-CTA
// conversion, no register staging).

namespace {

constexpr int S  = 2048;
constexpr int D  = 128;
constexpr int BM = 64;
constexpr int BN = 64;
constexpr int NTHREADS = 128;
constexpr float SCALE_F = 0.08838834764831845f;
constexpr size_t NELEM = (size_t)2 * 16 * 2048 * 128;   // 8,388,608

// fp16 tiles: 256B rows (128 halves). Swizzle: 16B chunks xor (row&7) per 128B block.
constexpr int SK_OFF = 0;                    // K' 64 x 256B = 16KB
constexpr int SV_OFF = 16384;                // V 2 x 64 x 256B = 32KB
constexpr int VBYTES = 16384;
constexpr int SP_OFF = SV_OFF + 2 * VBYTES;  // P 64 x 128B = 8KB
constexpr int SMEM_BYTES = SP_OFF + 8192;    // 57344

__device__ __half g_k16[NELEM];
__device__ __half g_v16[NELEM];

// ---- pre-pass: fp32 -> fp16 (K scaled) ----
__global__ void __launch_bounds__(256) cvt16(const float* __restrict__ K,
                                             const float* __restrict__ V) {
    const size_t i = ((size_t)blockIdx.x * 256 + threadIdx.x) * 4;
    float4 k4 = *reinterpret_cast<const float4*>(K + i);
    float4 v4 = *reinterpret_cast<const float4*>(V + i);
    __half2* ko = reinterpret_cast<__half2*>(g_k16 + i);
    __half2* vo = reinterpret_cast<__half2*>(g_v16 + i);
    ko[0] = __floats2half2_rn(k4.x * SCALE_F, k4.y * SCALE_F);
    ko[1] = __floats2half2_rn(k4.z * SCALE_F, k4.w * SCALE_F);
    vo[0] = __floats2half2_rn(v4.x, v4.y);
    vo[1] = __floats2half2_rn(v4.z, v4.w);
}

__device__ __forceinline__ uint32_t smem_u32(const void* p) {
    uint32_t a;
    asm("{ .reg .u64 t; cvta.to.shared.u64 t, %1; cvt.u32.u64 %0, t; }" : "=r"(a) : "l"(p));
    return a;
}
__device__ __forceinline__ uint32_t packh2(float lo, float hi) {
    uint32_t d;
    asm("cvt.rn.f16x2.f32 %0, %1, %2;" : "=r"(d) : "f"(hi), "f"(lo));
    return d;
}
__device__ __forceinline__ uint32_t swzoff(uint32_t row, uint32_t cb, uint32_t rowb) {
    uint32_t block = cb >> 7, rem = cb & 127;
    uint32_t chunk = rem >> 4, inner = rem & 15;
    return row * rowb + block * 128 + (((chunk ^ (row & 7)) << 4) | inner);
}
__device__ __forceinline__ void ldsm4(uint32_t r[4], uint32_t a) {
    asm volatile("ldmatrix.sync.aligned.m8n8.x4.shared.b16 {%0,%1,%2,%3}, [%4];"
                 : "=r"(r[0]), "=r"(r[1]), "=r"(r[2]), "=r"(r[3]) : "r"(a));
}
__device__ __forceinline__ void ldsm4t(uint32_t r[4], uint32_t a) {
    asm volatile("ldmatrix.sync.aligned.m8n8.x4.trans.shared.b16 {%0,%1,%2,%3}, [%4];"
                 : "=r"(r[0]), "=r"(r[1]), "=r"(r[2]), "=r"(r[3]) : "r"(a));
}
__device__ __forceinline__ void sts32(uint32_t a, uint32_t v) {
    asm volatile("st.shared.b32 [%0], %1;" :: "r"(a), "r"(v));
}
__device__ __forceinline__ void cpasync16(uint32_t dst, const void* src) {
    asm volatile("cp.async.cg.shared.global [%0], [%1], 16;" :: "r"(dst), "l"(src) : "memory");
}
__device__ __forceinline__ void cpasync_commit() {
    asm volatile("cp.async.commit_group;" ::: "memory");
}
__device__ __forceinline__ void cpasync_wait0() {
    asm volatile("cp.async.wait_group 0;" ::: "memory");
}
__device__ __forceinline__ void mma16(float* c, const uint32_t a[4],
                                      uint32_t b0, uint32_t b1) {
    asm volatile(
        "mma.sync.aligned.m16n8k16.row.col.f32.f16.f16.f32 "
        "{%0,%1,%2,%3}, {%4,%5,%6,%7}, {%8,%9}, {%0,%1,%2,%3};"
        : "+f"(c[0]), "+f"(c[1]), "+f"(c[2]), "+f"(c[3])
        : "r"(a[0]), "r"(a[1]), "r"(a[2]), "r"(a[3]), "r"(b0), "r"(b1));
}

__global__ __launch_bounds__(NTHREADS)
void fa_h16b(float* __restrict__ Og) {
    extern __shared__ __align__(1024) char smem[];
    const uint32_t sb = smem_u32(smem);
    const int tid  = threadIdx.x;
    const int wid  = tid >> 5;
    const int lane = tid & 31;
    const int g    = lane >> 2;
    const int tg   = lane & 3;
    const int mat  = lane >> 3;
    const int rr   = lane & 7;

    const int bh = blockIdx.y;
    const int qb = (int)gridDim.x - 1 - (int)blockIdx.x;   // longest first

    const __half* K16 = g_k16 + (size_t)bh * S * D;
    const __half* V16 = g_v16 + (size_t)bh * S * D;
    float*        Oh  = Og   + (size_t)bh * S * D;

    const int rj = (wid >> 1) * 32;   // GEMM1 j half
    const int ri = (wid & 1) * 32;    // i half
    const int dn = (wid >> 1) * 64;   // GEMM2 d half

    const uint32_t rowA = (uint32_t)(((mat & 1) << 3) + rr);
    const uint32_t cbA  = (uint32_t)((mat >> 1) << 4);
    const uint32_t rowB = (uint32_t)(((mat >> 1) << 3) + rr);
    const uint32_t cbB  = (uint32_t)((mat & 1) << 4);

    // ---- loop-invariant address tables (identical to R11) ----
    uint32_t swA1[4], swB1[4];
    #pragma unroll
    for (int r = 0; r < 4; ++r) {
        swA1[r] = swzoff(rowA, (uint32_t)r * 32 + cbA, 256) - rowA * 256;
        swB1[r] = swzoff(rowB, (uint32_t)r * 32 + cbB, 256) - rowB * 256;
    }
    const uint32_t vaC0 = (uint32_t)(rj +      rowA) * 256;
    const uint32_t vaC1 = (uint32_t)(rj + 16 + rowA) * 256;
    const uint32_t kb0  = sb + SK_OFF + (uint32_t)(ri +      rowB) * 256;
    const uint32_t kb1  = sb + SK_OFF + (uint32_t)(ri + 16 + rowB) * 256;
    uint32_t ptb[2];
    #pragma unroll
    for (int ih = 0; ih < 2; ++ih)
        ptb[ih] = sb + SP_OFF + swzoff(rowB, (uint32_t)(ri * 2 + ih * 32) + cbB, 128);
    uint32_t remVT[4];
    #pragma unroll
    for (int dp = 0; dp < 4; ++dp)
        remVT[dp] = swzoff(rowA, (uint32_t)(dn * 2 + dp * 32) + cbA, 256) - rowA * 256;
    const uint32_t ri8 = (uint32_t)(ri >> 3);
    uint32_t psb[2][2];
    #pragma unroll
    for (int jh = 0; jh < 2; ++jh) {
        psb[jh][0] = sb + SP_OFF + (uint32_t)(rj + jh * 16 + g) * 128 + (uint32_t)tg * 4;
        psb[jh][1] = psb[jh][0] + 8 * 128;
    }
    // tile-load mapping: thread owns row vr, 128B-block vh, 8 chunks of 16B
    const int vr  = tid >> 1;
    const int vh  = tid & 1;
    const uint32_t vrl = (uint32_t)(vr & 7);
    const uint32_t vstBase = (uint32_t)vr * 256 + (uint32_t)vh * 128;

    // ---- prologue: cp.async K' block + V tile 0 (both already fp16) ----
    {
        const __half* ks = K16 + (size_t)(qb * BM + vr) * D + vh * 64;
        const __half* vs = V16 + (size_t)vr * D + vh * 64;
        #pragma unroll
        for (int q = 0; q < 8; ++q) {
            const uint32_t off = vstBase + (uint32_t)(((uint32_t)q ^ vrl) << 4);
            cpasync16(sb + SK_OFF + off, ks + q * 8);
            cpasync16(sb + SV_OFF + off, vs + q * 8);
        }
        cpasync_commit();
    }

    float oacc[2][8][4];
    #pragma unroll
    for (int ih = 0; ih < 2; ++ih)
        #pragma unroll
        for (int dg = 0; dg < 8; ++dg) {
            oacc[ih][dg][0] = 0.f; oacc[ih][dg][1] = 0.f;
            oacc[ih][dg][2] = 0.f; oacc[ih][dg][3] = 0.f;
        }
    float lsum[4][2];
    #pragma unroll
    for (int ng = 0; ng < 4; ++ng) { lsum[ng][0] = 0.f; lsum[ng][1] = 0.f; }

    const __half* gv = V16 + (size_t)(BN + vr) * D + vh * 64;   // V(jb+1) source

    cpasync_wait0();
    __syncthreads();   // K' + V0 visible

    for (int jb = 0; jb <= qb; ++jb) {
        const int cur = jb & 1;
        const uint32_t svc = sb + SV_OFF + (uint32_t)cur * VBYTES;

        // ---- prefetch V(jb+1) (fp16, cp.async) ----
        if (jb < qb) {
            const uint32_t dbase = sb + SV_OFF + (uint32_t)(cur ^ 1) * VBYTES + vstBase;
            #pragma unroll
            for (int q = 0; q < 8; ++q)
                cpasync16(dbase + (uint32_t)(((uint32_t)q ^ vrl) << 4), gv + q * 8);
            cpasync_commit();
            gv += (size_t)BN * D;
        }

        // ---- GEMM1: S^T[32j x 32i] = V[32j x 128d] * K'^T ----
        const uint32_t va0 = svc + vaC0;
        const uint32_t va1 = svc + vaC1;
        float sacc[2][4][4];
        #pragma unroll
        for (int jh = 0; jh < 2; ++jh)
            #pragma unroll
            for (int ng = 0; ng < 4; ++ng) {
                sacc[jh][ng][0] = 0.f; sacc[jh][ng][1] = 0.f;
                sacc[jh][ng][2] = 0.f; sacc[jh][ng][3] = 0.f;
            }
        #pragma unroll
        for (int kt = 0; kt < 8; ++kt) {
            const uint32_t offA = swA1[kt & 3] + (uint32_t)((kt >> 2) * 128);
            const uint32_t offB = swB1[kt & 3] + (uint32_t)((kt >> 2) * 128);
            uint32_t a[2][4], b[2][4];
            ldsm4(a[0], va0 + offA);
            ldsm4(a[1], va1 + offA);
            ldsm4(b[0], kb0 + offB);
            ldsm4(b[1], kb1 + offB);
            #pragma unroll
            for (int jh = 0; jh < 2; ++jh)
                #pragma unroll
                for (int ng = 0; ng < 4; ++ng)
                    mma16(sacc[jh][ng], a[jh],
                          b[ng >> 1][(ng & 1) * 2], b[ng >> 1][(ng & 1) * 2 + 1]);
        }

        // ---- softmax: mask, exp, lsum, store P (j-major f16x2) ----
        #pragma unroll
        for (int jh = 0; jh < 2; ++jh) {
            const int j0 = jb * BN + rj + jh * 16 + g;
            const int j1 = j0 + 8;
            #pragma unroll
            for (int ng = 0; ng < 4; ++ng) {
                const int i0 = qb * BM + ri + ng * 8 + 2 * tg;
                float p00 = (j0 <= i0)     ? __expf(sacc[jh][ng][0]) : 0.f;
                float p01 = (j0 <= i0 + 1) ? __expf(sacc[jh][ng][1]) : 0.f;
                float p10 = (j1 <= i0)     ? __expf(sacc[jh][ng][2]) : 0.f;
                float p11 = (j1 <= i0 + 1) ? __expf(sacc[jh][ng][3]) : 0.f;
                lsum[ng][0] += p00 + p10;
                lsum[ng][1] += p01 + p11;
                const uint32_t rem = ((ri8 + (uint32_t)ng) ^ (uint32_t)g) << 4;
                sts32(psb[jh][0] + rem, packh2(p00, p01));
                sts32(psb[jh][1] + rem, packh2(p10, p11));
            }
        }
        __syncthreads();   // P visible

        // ---- GEMM2: O[32i x 64d] += P[32i x 64j] * V[64j x 64d] ----
        const uint32_t vtb = svc + rowA * 256;
        #pragma unroll
        for (int kt = 0; kt < 4; ++kt) {
            uint32_t aP[2][4], bV[4][4];
            ldsm4t(aP[0], ptb[0] + (uint32_t)kt * 2048);
            ldsm4t(aP[1], ptb[1] + (uint32_t)kt * 2048);
            #pragma unroll
            for (int dp = 0; dp < 4; ++dp)
                ldsm4t(bV[dp], vtb + (uint32_t)kt * 4096 + remVT[dp]);
            #pragma unroll
            for (int ih = 0; ih < 2; ++ih)
                #pragma unroll
                for (int dg = 0; dg < 8; ++dg)
                    mma16(oacc[ih][dg], aP[ih],
                          bV[dg >> 1][(dg & 1) * 2], bV[dg >> 1][(dg & 1) * 2 + 1]);
        }

        cpasync_wait0();
        __syncthreads();   // next V landed; P / sV[cur] free
    }

    // ---- epilogue: reduce lsum over j, then across j-half warps via smem ----
    #pragma unroll
    for (int ng = 0; ng < 4; ++ng)
        #pragma unroll
        for (int c = 0; c < 2; ++c) {
            float v = lsum[ng][c];
            v += __shfl_xor_sync(0xffffffffu, v, 4);
            v += __shfl_xor_sync(0xffffffffu, v, 8);
            v += __shfl_xor_sync(0xffffffffu, v, 16);
            lsum[ng][c] = v;
        }
    float* lbuf = reinterpret_cast<float*>(smem + SP_OFF);
    if (g == 0) {
        #pragma unroll
        for (int ng = 0; ng < 4; ++ng) {
            lbuf[(wid >> 1) * 64 + ri + ng * 8 + 2 * tg]     = lsum[ng][0];
            lbuf[(wid >> 1) * 64 + ri + ng * 8 + 2 * tg + 1] = lsum[ng][1];
        }
    }
    __syncthreads();

    // ---- normalize + store O ----
    #pragma unroll
    for (int ih = 0; ih < 2; ++ih) {
        const int il0 = ri + ih * 16 + g;
        const int il1 = il0 + 8;
        const float inv0 = 1.f / (lbuf[il0] + lbuf[64 + il0]);
        const float inv1 = 1.f / (lbuf[il1] + lbuf[64 + il1]);
        float* o0 = Oh + (size_t)(qb * BM + il0) * D + dn + 2 * tg;
        float* o1 = Oh + (size_t)(qb * BM + il1) * D + dn + 2 * tg;
        #pragma unroll
        for (int dg = 0; dg < 8; ++dg) {
            float2 w0 = make_float2(oacc[ih][dg][0] * inv0, oacc[ih][dg][1] * inv0);
            float2 w1 = make_float2(oacc[ih][dg][2] * inv1, oacc[ih][dg][3] * inv1);
            *reinterpret_cast<float2*>(o0 + dg * 8) = w0;
            *reinterpret_cast<float2*>(o1 + dg * 8) = w1;
        }
    }
}

}  // namespace

extern "C" void kernel_launch(void* const* d_in, const int* /*in_sizes*/, int /*n_in*/,
                              void* d_out, int /*out_size*/) {
    // inputs: d_in[0]=q (unused by reference), d_in[1]=k, d_in[2]=v
    const float* k = reinterpret_cast<const float*>(d_in[1]);
    const float* v = reinterpret_cast<const float*>(d_in[2]);
    float* o = reinterpret_cast<float*>(d_out);

    // pre-pass: K*scale and V -> fp16 scratch (8,388,608 elems / 4 per thread)
    cvt16<<<(unsigned)(NELEM / 4 / 256), 256>>>(k, v);

    cudaFuncSetAttribute(fa_h16b,
                         cudaFuncAttributeMaxDynamicSharedMemorySize, SMEM_BYTES);
    dim3 grid(S / BM, 32);
    fa_h16b<<<grid, NTHREADS, SMEM_BYTES>>>(o);
}

// round 13
// speedup vs baseline: 1.9999x; 1.1008x over previous
#include <cuda_runtime.h>
#include <cuda_fp16.h>
#include <cstdint>
#include <cstddef>

// Attend_62534723830373: out = softmax(causal(K V^T / sqrt(128))) @ V  (q unused)
// [2,16,2048,128] fp32. fp16 m16n8k16 flash attention (R12 math, bit-identical).
// Pre-pass converts K*scale and V to fp16 once into __device__ scratch; flash
// kernel streams fp16 tiles via cp.async. R13 change: __launch_bounds__(128,3)
// -> 3 CTAs/SM (12 warps) for latency hiding. Everything else identical to R12.

namespace {

constexpr int S  = 2048;
constexpr int D  = 128;
constexpr int BM = 64;
constexpr int BN = 64;
constexpr int NTHREADS = 128;
constexpr float SCALE_F = 0.08838834764831845f;
constexpr size_t NELEM = (size_t)2 * 16 * 2048 * 128;   // 8,388,608

// fp16 tiles: 256B rows (128 halves). Swizzle: 16B chunks xor (row&7) per 128B block.
constexpr int SK_OFF = 0;                    // K' 64 x 256B = 16KB
constexpr int SV_OFF = 16384;                // V 2 x 64 x 256B = 32KB
constexpr int VBYTES = 16384;
constexpr int SP_OFF = SV_OFF + 2 * VBYTES;  // P 64 x 128B = 8KB
constexpr int SMEM_BYTES = SP_OFF + 8192;    // 57344 -> 3 CTAs/SM

__device__ __half g_k16[NELEM];
__device__ __half g_v16[NELEM];

// ---- pre-pass: fp32 -> fp16 (K scaled) ----
__global__ void __launch_bounds__(256) cvt16(const float* __restrict__ K,
                                             const float* __restrict__ V) {
    const size_t i = ((size_t)blockIdx.x * 256 + threadIdx.x) * 4;
    float4 k4 = *reinterpret_cast<const float4*>(K + i);
    float4 v4 = *reinterpret_cast<const float4*>(V + i);
    __half2* ko = reinterpret_cast<__half2*>(g_k16 + i);
    __half2* vo = reinterpret_cast<__half2*>(g_v16 + i);
    ko[0] = __floats2half2_rn(k4.x * SCALE_F, k4.y * SCALE_F);
    ko[1] = __floats2half2_rn(k4.z * SCALE_F, k4.w * SCALE_F);
    vo[0] = __floats2half2_rn(v4.x, v4.y);
    vo[1] = __floats2half2_rn(v4.z, v4.w);
}

__device__ __forceinline__ uint32_t smem_u32(const void* p) {
    uint32_t a;
    asm("{ .reg .u64 t; cvta.to.shared.u64 t, %1; cvt.u32.u64 %0, t; }" : "=r"(a) : "l"(p));
    return a;
}
__device__ __forceinline__ uint32_t packh2(float lo, float hi) {
    uint32_t d;
    asm("cvt.rn.f16x2.f32 %0, %1, %2;" : "=r"(d) : "f"(hi), "f"(lo));
    return d;
}
__device__ __forceinline__ uint32_t swzoff(uint32_t row, uint32_t cb, uint32_t rowb) {
    uint32_t block = cb >> 7, rem = cb & 127;
    uint32_t chunk = rem >> 4, inner = rem & 15;
    return row * rowb + block * 128 + (((chunk ^ (row & 7)) << 4) | inner);
}
__device__ __forceinline__ void ldsm4(uint32_t r[4], uint32_t a) {
    asm volatile("ldmatrix.sync.aligned.m8n8.x4.shared.b16 {%0,%1,%2,%3}, [%4];"
                 : "=r"(r[0]), "=r"(r[1]), "=r"(r[2]), "=r"(r[3]) : "r"(a));
}
__device__ __forceinline__ void ldsm4t(uint32_t r[4], uint32_t a) {
    asm volatile("ldmatrix.sync.aligned.m8n8.x4.trans.shared.b16 {%0,%1,%2,%3}, [%4];"
                 : "=r"(r[0]), "=r"(r[1]), "=r"(r[2]), "=r"(r[3]) : "r"(a));
}
__device__ __forceinline__ void sts32(uint32_t a, uint32_t v) {
    asm volatile("st.shared.b32 [%0], %1;" :: "r"(a), "r"(v));
}
__device__ __forceinline__ void cpasync16(uint32_t dst, const void* src) {
    asm volatile("cp.async.cg.shared.global [%0], [%1], 16;" :: "r"(dst), "l"(src) : "memory");
}
__device__ __forceinline__ void cpasync_commit() {
    asm volatile("cp.async.commit_group;" ::: "memory");
}
__device__ __forceinline__ void cpasync_wait0() {
    asm volatile("cp.async.wait_group 0;" ::: "memory");
}
__device__ __forceinline__ void mma16(float* c, const uint32_t a[4],
                                      uint32_t b0, uint32_t b1) {
    asm volatile(
        "mma.sync.aligned.m16n8k16.row.col.f32.f16.f16.f32 "
        "{%0,%1,%2,%3}, {%4,%5,%6,%7}, {%8,%9}, {%0,%1,%2,%3};"
        : "+f"(c[0]), "+f"(c[1]), "+f"(c[2]), "+f"(c[3])
        : "r"(a[0]), "r"(a[1]), "r"(a[2]), "r"(a[3]), "r"(b0), "r"(b1));
}

__global__ __launch_bounds__(NTHREADS, 3)
void fa_h16c(float* __restrict__ Og) {
    extern __shared__ __align__(1024) char smem[];
    const uint32_t sb = smem_u32(smem);
    const int tid  = threadIdx.x;
    const int wid  = tid >> 5;
    const int lane = tid & 31;
    const int g    = lane >> 2;
    const int tg   = lane & 3;
    const int mat  = lane >> 3;
    const int rr   = lane & 7;

    const int bh = blockIdx.y;
    const int qb = (int)gridDim.x - 1 - (int)blockIdx.x;   // longest first

    const __half* K16 = g_k16 + (size_t)bh * S * D;
    const __half* V16 = g_v16 + (size_t)bh * S * D;
    float*        Oh  = Og   + (size_t)bh * S * D;

    const int rj = (wid >> 1) * 32;   // GEMM1 j half
    const int ri = (wid & 1) * 32;    // i half
    const int dn = (wid >> 1) * 64;   // GEMM2 d half

    const uint32_t rowA = (uint32_t)(((mat & 1) << 3) + rr);
    const uint32_t cbA  = (uint32_t)((mat >> 1) << 4);
    const uint32_t rowB = (uint32_t)(((mat >> 1) << 3) + rr);
    const uint32_t cbB  = (uint32_t)((mat & 1) << 4);

    // ---- loop-invariant address tables (identical to R12) ----
    uint32_t swA1[4], swB1[4];
    #pragma unroll
    for (int r = 0; r < 4; ++r) {
        swA1[r] = swzoff(rowA, (uint32_t)r * 32 + cbA, 256) - rowA * 256;
        swB1[r] = swzoff(rowB, (uint32_t)r * 32 + cbB, 256) - rowB * 256;
    }
    const uint32_t vaC0 = (uint32_t)(rj +      rowA) * 256;
    const uint32_t vaC1 = (uint32_t)(rj + 16 + rowA) * 256;
    const uint32_t kb0  = sb + SK_OFF + (uint32_t)(ri +      rowB) * 256;
    const uint32_t kb1  = sb + SK_OFF + (uint32_t)(ri + 16 + rowB) * 256;
    uint32_t ptb[2];
    #pragma unroll
    for (int ih = 0; ih < 2; ++ih)
        ptb[ih] = sb + SP_OFF + swzoff(rowB, (uint32_t)(ri * 2 + ih * 32) + cbB, 128);
    uint32_t remVT[4];
    #pragma unroll
    for (int dp = 0; dp < 4; ++dp)
        remVT[dp] = swzoff(rowA, (uint32_t)(dn * 2 + dp * 32) + cbA, 256) - rowA * 256;
    const uint32_t ri8 = (uint32_t)(ri >> 3);
    uint32_t psb[2][2];
    #pragma unroll
    for (int jh = 0; jh < 2; ++jh) {
        psb[jh][0] = sb + SP_OFF + (uint32_t)(rj + jh * 16 + g) * 128 + (uint32_t)tg * 4;
        psb[jh][1] = psb[jh][0] + 8 * 128;
    }
    // tile-load mapping: thread owns row vr, 128B-block vh, 8 chunks of 16B
    const int vr  = tid >> 1;
    const int vh  = tid & 1;
    const uint32_t vrl = (uint32_t)(vr & 7);
    const uint32_t vstBase = (uint32_t)vr * 256 + (uint32_t)vh * 128;

    // ---- prologue: cp.async K' block + V tile 0 (both already fp16) ----
    {
        const __half* ks = K16 + (size_t)(qb * BM + vr) * D + vh * 64;
        const __half* vs = V16 + (size_t)vr * D + vh * 64;
        #pragma unroll
        for (int q = 0; q < 8; ++q) {
            const uint32_t off = vstBase + (uint32_t)(((uint32_t)q ^ vrl) << 4);
            cpasync16(sb + SK_OFF + off, ks + q * 8);
            cpasync16(sb + SV_OFF + off, vs + q * 8);
        }
        cpasync_commit();
    }

    float oacc[2][8][4];
    #pragma unroll
    for (int ih = 0; ih < 2; ++ih)
        #pragma unroll
        for (int dg = 0; dg < 8; ++dg) {
            oacc[ih][dg][0] = 0.f; oacc[ih][dg][1] = 0.f;
            oacc[ih][dg][2] = 0.f; oacc[ih][dg][3] = 0.f;
        }
    float lsum[4][2];
    #pragma unroll
    for (int ng = 0; ng < 4; ++ng) { lsum[ng][0] = 0.f; lsum[ng][1] = 0.f; }

    const __half* gv = V16 + (size_t)(BN + vr) * D + vh * 64;   // V(jb+1) source

    cpasync_wait0();
    __syncthreads();   // K' + V0 visible

    for (int jb = 0; jb <= qb; ++jb) {
        const int cur = jb & 1;
        const uint32_t svc = sb + SV_OFF + (uint32_t)cur * VBYTES;

        // ---- prefetch V(jb+1) (fp16, cp.async) ----
        if (jb < qb) {
            const uint32_t dbase = sb + SV_OFF + (uint32_t)(cur ^ 1) * VBYTES + vstBase;
            #pragma unroll
            for (int q = 0; q < 8; ++q)
                cpasync16(dbase + (uint32_t)(((uint32_t)q ^ vrl) << 4), gv + q * 8);
            cpasync_commit();
            gv += (size_t)BN * D;
        }

        // ---- GEMM1: S^T[32j x 32i] = V[32j x 128d] * K'^T ----
        const uint32_t va0 = svc + vaC0;
        const uint32_t va1 = svc + vaC1;
        float sacc[2][4][4];
        #pragma unroll
        for (int jh = 0; jh < 2; ++jh)
            #pragma unroll
            for (int ng = 0; ng < 4; ++ng) {
                sacc[jh][ng][0] = 0.f; sacc[jh][ng][1] = 0.f;
                sacc[jh][ng][2] = 0.f; sacc[jh][ng][3] = 0.f;
            }
        #pragma unroll
        for (int kt = 0; kt < 8; ++kt) {
            const uint32_t offA = swA1[kt & 3] + (uint32_t)((kt >> 2) * 128);
            const uint32_t offB = swB1[kt & 3] + (uint32_t)((kt >> 2) * 128);
            uint32_t a[2][4], b[2][4];
            ldsm4(a[0], va0 + offA);
            ldsm4(a[1], va1 + offA);
            ldsm4(b[0], kb0 + offB);
            ldsm4(b[1], kb1 + offB);
            #pragma unroll
            for (int jh = 0; jh < 2; ++jh)
                #pragma unroll
                for (int ng = 0; ng < 4; ++ng)
                    mma16(sacc[jh][ng], a[jh],
                          b[ng >> 1][(ng & 1) * 2], b[ng >> 1][(ng & 1) * 2 + 1]);
        }

        // ---- softmax: mask, exp, lsum, store P (j-major f16x2) ----
        #pragma unroll
        for (int jh = 0; jh < 2; ++jh) {
            const int j0 = jb * BN + rj + jh * 16 + g;
            const int j1 = j0 + 8;
            #pragma unroll
            for (int ng = 0; ng < 4; ++ng) {
                const int i0 = qb * BM + ri + ng * 8 + 2 * tg;
                float p00 = (j0 <= i0)     ? __expf(sacc[jh][ng][0]) : 0.f;
                float p01 = (j0 <= i0 + 1) ? __expf(sacc[jh][ng][1]) : 0.f;
                float p10 = (j1 <= i0)     ? __expf(sacc[jh][ng][2]) : 0.f;
                float p11 = (j1 <= i0 + 1) ? __expf(sacc[jh][ng][3]) : 0.f;
                lsum[ng][0] += p00 + p10;
                lsum[ng][1] += p01 + p11;
                const uint32_t rem = ((ri8 + (uint32_t)ng) ^ (uint32_t)g) << 4;
                sts32(psb[jh][0] + rem, packh2(p00, p01));
                sts32(psb[jh][1] + rem, packh2(p10, p11));
            }
        }
        __syncthreads();   // P visible

        // ---- GEMM2: O[32i x 64d] += P[32i x 64j] * V[64j x 64d] ----
        const uint32_t vtb = svc + rowA * 256;
        #pragma unroll
        for (int kt = 0; kt < 4; ++kt) {
            uint32_t aP[2][4], bV[4][4];
            ldsm4t(aP[0], ptb[0] + (uint32_t)kt * 2048);
            ldsm4t(aP[1], ptb[1] + (uint32_t)kt * 2048);
            #pragma unroll
            for (int dp = 0; dp < 4; ++dp)
                ldsm4t(bV[dp], vtb + (uint32_t)kt * 4096 + remVT[dp]);
            #pragma unroll
            for (int ih = 0; ih < 2; ++ih)
                #pragma unroll
                for (int dg = 0; dg < 8; ++dg)
                    mma16(oacc[ih][dg], aP[ih],
                          bV[dg >> 1][(dg & 1) * 2], bV[dg >> 1][(dg & 1) * 2 + 1]);
        }

        cpasync_wait0();
        __syncthreads();   // next V landed; P / sV[cur] free
    }

    // ---- epilogue: reduce lsum over j, then across j-half warps via smem ----
    #pragma unroll
    for (int ng = 0; ng < 4; ++ng)
        #pragma unroll
        for (int c = 0; c < 2; ++c) {
            float v = lsum[ng][c];
            v += __shfl_xor_sync(0xffffffffu, v, 4);
            v += __shfl_xor_sync(0xffffffffu, v, 8);
            v += __shfl_xor_sync(0xffffffffu, v, 16);
            lsum[ng][c] = v;
        }
    float* lbuf = reinterpret_cast<float*>(smem + SP_OFF);
    if (g == 0) {
        #pragma unroll
        for (int ng = 0; ng < 4; ++ng) {
            lbuf[(wid >> 1) * 64 + ri + ng * 8 + 2 * tg]     = lsum[ng][0];
            lbuf[(wid >> 1) * 64 + ri + ng * 8 + 2 * tg + 1] = lsum[ng][1];
        }
    }
    __syncthreads();

    // ---- normalize + store O ----
    #pragma unroll
    for (int ih = 0; ih < 2; ++ih) {
        const int il0 = ri + ih * 16 + g;
        const int il1 = il0 + 8;
        const float inv0 = 1.f / (lbuf[il0] + lbuf[64 + il0]);
        const float inv1 = 1.f / (lbuf[il1] + lbuf[64 + il1]);
        float* o0 = Oh + (size_t)(qb * BM + il0) * D + dn + 2 * tg;
        float* o1 = Oh + (size_t)(qb * BM + il1) * D + dn + 2 * tg;
        #pragma unroll
        for (int dg = 0; dg < 8; ++dg) {
            float2 w0 = make_float2(oacc[ih][dg][0] * inv0, oacc[ih][dg][1] * inv0);
            float2 w1 = make_float2(oacc[ih][dg][2] * inv1, oacc[ih][dg][3] * inv1);
            *reinterpret_cast<float2*>(o0 + dg * 8) = w0;
            *reinterpret_cast<float2*>(o1 + dg * 8) = w1;
        }
    }
}

}  // namespace

extern "C" void kernel_launch(void* const* d_in, const int* /*in_sizes*/, int /*n_in*/,
                              void* d_out, int /*out_size*/) {
    // inputs: d_in[0]=q (unused by reference), d_in[1]=k, d_in[2]=v
    const float* k = reinterpret_cast<const float*>(d_in[1]);
    const float* v = reinterpret_cast<const float*>(d_in[2]);
    float* o = reinterpret_cast<float*>(d_out);

    // pre-pass: K*scale and V -> fp16 scratch
    cvt16<<<(unsigned)(NELEM / 4 / 256), 256>>>(k, v);

    cudaFuncSetAttribute(fa_h16c,
                         cudaFuncAttributeMaxDynamicSharedMemorySize, SMEM_BYTES);
    dim3 grid(S / BM, 32);
    fa_h16c<<<grid, NTHREADS, SMEM_BYTES>>>(o);
}

// round 14
// speedup vs baseline: 2.0878x; 1.0440x over previous
#include <cuda_runtime.h>
#include <cuda_fp16.h>
#include <cstdint>
#include <cstddef>

// Attend_62534723830373: out = softmax(causal(K V^T / sqrt(128))) @ V  (q unused)
// [2,16,2048,128] fp32. fp16 m16n8k16 flash attention. Pre-pass converts K*scale
// and V to fp16 scratch once. R14: normal-orientation S (warp = 16i x 64j); the
// fp16 C-fragment of GEMM1 packs DIRECTLY into GEMM2's A-fragments (P never in
// smem, no shuffles), so each KV iteration has ONE barrier and no P traffic.

namespace {

constexpr int S  = 2048;
constexpr int D  = 128;
constexpr int BM = 64;
constexpr int BN = 64;
constexpr int NTHREADS = 128;
constexpr float SCALE_F = 0.08838834764831845f;
constexpr size_t NELEM = (size_t)2 * 16 * 2048 * 128;

// fp16 tiles: 256B rows (128 halves). Swizzle: 16B chunks xor (row&7) per 128B block.
constexpr int SK_OFF = 0;                    // K' 64 x 256B = 16KB
constexpr int SV_OFF = 16384;                // V 2 x 64 x 256B = 32KB
constexpr int VBYTES = 16384;
constexpr int SMEM_BYTES = SV_OFF + 2 * VBYTES;   // 49152 -> 3 CTAs/SM

__device__ __half g_k16[NELEM];
__device__ __half g_v16[NELEM];

__global__ void __launch_bounds__(256) cvt16(const float* __restrict__ K,
                                             const float* __restrict__ V) {
    const size_t i = ((size_t)blockIdx.x * 256 + threadIdx.x) * 4;
    float4 k4 = *reinterpret_cast<const float4*>(K + i);
    float4 v4 = *reinterpret_cast<const float4*>(V + i);
    __half2* ko = reinterpret_cast<__half2*>(g_k16 + i);
    __half2* vo = reinterpret_cast<__half2*>(g_v16 + i);
    ko[0] = __floats2half2_rn(k4.x * SCALE_F, k4.y * SCALE_F);
    ko[1] = __floats2half2_rn(k4.z * SCALE_F, k4.w * SCALE_F);
    vo[0] = __floats2half2_rn(v4.x, v4.y);
    vo[1] = __floats2half2_rn(v4.z, v4.w);
}

__device__ __forceinline__ uint32_t smem_u32(const void* p) {
    uint32_t a;
    asm("{ .reg .u64 t; cvta.to.shared.u64 t, %1; cvt.u32.u64 %0, t; }" : "=r"(a) : "l"(p));
    return a;
}
__device__ __forceinline__ uint32_t packh2(float lo, float hi) {
    uint32_t d;
    asm("cvt.rn.f16x2.f32 %0, %1, %2;" : "=r"(d) : "f"(hi), "f"(lo));
    return d;
}
__device__ __forceinline__ uint32_t swzoff(uint32_t row, uint32_t cb, uint32_t rowb) {
    uint32_t block = cb >> 7, rem = cb & 127;
    uint32_t chunk = rem >> 4, inner = rem & 15;
    return row * rowb + block * 128 + (((chunk ^ (row & 7)) << 4) | inner);
}
__device__ __forceinline__ void ldsm4(uint32_t r[4], uint32_t a) {
    asm volatile("ldmatrix.sync.aligned.m8n8.x4.shared.b16 {%0,%1,%2,%3}, [%4];"
                 : "=r"(r[0]), "=r"(r[1]), "=r"(r[2]), "=r"(r[3]) : "r"(a));
}
__device__ __forceinline__ void ldsm4t(uint32_t r[4], uint32_t a) {
    asm volatile("ldmatrix.sync.aligned.m8n8.x4.trans.shared.b16 {%0,%1,%2,%3}, [%4];"
                 : "=r"(r[0]), "=r"(r[1]), "=r"(r[2]), "=r"(r[3]) : "r"(a));
}
__device__ __forceinline__ void cpasync16(uint32_t dst, const void* src) {
    asm volatile("cp.async.cg.shared.global [%0], [%1], 16;" :: "r"(dst), "l"(src) : "memory");
}
__device__ __forceinline__ void cpasync_commit() {
    asm volatile("cp.async.commit_group;" ::: "memory");
}
__device__ __forceinline__ void cpasync_wait0() {
    asm volatile("cp.async.wait_group 0;" ::: "memory");
}
__device__ __forceinline__ void mma16(float* c,
                                      uint32_t a0, uint32_t a1, uint32_t a2, uint32_t a3,
                                      uint32_t b0, uint32_t b1) {
    asm volatile(
        "mma.sync.aligned.m16n8k16.row.col.f32.f16.f16.f32 "
        "{%0,%1,%2,%3}, {%4,%5,%6,%7}, {%8,%9}, {%0,%1,%2,%3};"
        : "+f"(c[0]), "+f"(c[1]), "+f"(c[2]), "+f"(c[3])
        : "r"(a0), "r"(a1), "r"(a2), "r"(a3), "r"(b0), "r"(b1));
}

__global__ __launch_bounds__(NTHREADS, 3)
void fa_regP(float* __restrict__ Og) {
    extern __shared__ __align__(1024) char smem[];
    const uint32_t sb = smem_u32(smem);
    const int tid  = threadIdx.x;
    const int wid  = tid >> 5;
    const int lane = tid & 31;
    const int g    = lane >> 2;
    const int tg   = lane & 3;
    const int mat  = lane >> 3;
    const int rr   = lane & 7;

    const int bh = blockIdx.y;
    const int qb = (int)gridDim.x - 1 - (int)blockIdx.x;   // longest first

    const __half* K16 = g_k16 + (size_t)bh * S * D;
    const __half* V16 = g_v16 + (size_t)bh * S * D;
    float*        Oh  = Og   + (size_t)bh * S * D;

    const int ri  = wid * 16;             // warp's query rows
    const int gi0 = qb * BM + ri + g;     // thread's global rows
    const int gi1 = gi0 + 8;

    // ldsm lane-address components (A-style and B-style, proven R12/R13)
    const uint32_t rowA = (uint32_t)(((mat & 1) << 3) + rr);
    const uint32_t cbA  = (uint32_t)((mat >> 1) << 4);
    const uint32_t rowB = (uint32_t)(((mat >> 1) << 3) + rr);
    const uint32_t cbB  = (uint32_t)((mat & 1) << 4);

    // ---- loop-invariant address tables ----
    uint32_t swA1[4], swB1[4];             // GEMM1 kt remainders (256B rows)
    #pragma unroll
    for (int r = 0; r < 4; ++r) {
        swA1[r] = swzoff(rowA, (uint32_t)r * 32 + cbA, 256) - rowA * 256;
        swB1[r] = swzoff(rowB, (uint32_t)r * 32 + cbB, 256) - rowB * 256;
    }
    const uint32_t ka = sb + SK_OFF + (uint32_t)(ri + rowA) * 256;   // GEMM1 A (K')
    uint32_t vbC[4];                                                 // GEMM1 B (V) + svc
    #pragma unroll
    for (int q = 0; q < 4; ++q)
        vbC[q] = (uint32_t)(q * 16 + rowB) * 256;
    // GEMM2 B (V j-major, trans): addr = svc + rowA*256 + kt*4096 + remVT[dp]
    uint32_t remVT[8];
    #pragma unroll
    for (int dp = 0; dp < 8; ++dp)
        remVT[dp] = swzoff(rowA, (uint32_t)(dp * 32) + cbA, 256) - rowA * 256;

    // tile-load mapping (cp.async): thread owns row vr, 128B block vh
    const int vr  = tid >> 1;
    const int vh  = tid & 1;
    const uint32_t vrl = (uint32_t)(vr & 7);
    const uint32_t vstBase = (uint32_t)vr * 256 + (uint32_t)vh * 128;

    // ---- prologue: cp.async K' block + V tile 0 ----
    {
        const __half* ks = K16 + (size_t)(qb * BM + vr) * D + vh * 64;
        const __half* vs = V16 + (size_t)vr * D + vh * 64;
        #pragma unroll
        for (int q = 0; q < 8; ++q) {
            const uint32_t off = vstBase + (uint32_t)(((uint32_t)q ^ vrl) << 4);
            cpasync16(sb + SK_OFF + off, ks + q * 8);
            cpasync16(sb + SV_OFF + off, vs + q * 8);
        }
        cpasync_commit();
    }

    float oacc[16][4];
    #pragma unroll
    for (int dg = 0; dg < 16; ++dg) {
        oacc[dg][0] = 0.f; oacc[dg][1] = 0.f; oacc[dg][2] = 0.f; oacc[dg][3] = 0.f;
    }
    float ls0 = 0.f, ls1 = 0.f;

    const __half* gv = V16 + (size_t)(BN + vr) * D + vh * 64;   // V(jb+1) source

    cpasync_wait0();
    __syncthreads();   // K' + V0 visible

    for (int jb = 0; jb <= qb; ++jb) {
        const int cur = jb & 1;
        const uint32_t svc = sb + SV_OFF + (uint32_t)cur * VBYTES;

        // ---- prefetch V(jb+1) ----
        if (jb < qb) {
            const uint32_t dbase = sb + SV_OFF + (uint32_t)(cur ^ 1) * VBYTES + vstBase;
            #pragma unroll
            for (int q = 0; q < 8; ++q)
                cpasync16(dbase + (uint32_t)(((uint32_t)q ^ vrl) << 4), gv + q * 8);
            cpasync_commit();
            gv += (size_t)BN * D;
        }

        // ---- GEMM1: S[16i x 64j] = K'[16i x 128d] * V^T ----
        float sacc[8][4];
        #pragma unroll
        for (int jt = 0; jt < 8; ++jt) {
            sacc[jt][0] = 0.f; sacc[jt][1] = 0.f; sacc[jt][2] = 0.f; sacc[jt][3] = 0.f;
        }
        #pragma unroll
        for (int kt = 0; kt < 8; ++kt) {
            const uint32_t offA = swA1[kt & 3] + (uint32_t)((kt >> 2) * 128);
            const uint32_t offB = swB1[kt & 3] + (uint32_t)((kt >> 2) * 128);
            uint32_t a[4], b[4][4];
            ldsm4(a, ka + offA);
            #pragma unroll
            for (int q = 0; q < 4; ++q)
                ldsm4(b[q], svc + vbC[q] + offB);
            #pragma unroll
            for (int jt = 0; jt < 8; ++jt)
                mma16(sacc[jt], a[0], a[1], a[2], a[3],
                      b[jt >> 1][(jt & 1) * 2], b[jt >> 1][(jt & 1) * 2 + 1]);
        }

        // ---- softmax in registers: mask, exp, lsum; pack C-frags -> A-frags ----
        uint32_t pvA[8], pvB[8];   // row g / row g+8 f16x2 pairs per j8-tile
        #pragma unroll
        for (int jt = 0; jt < 8; ++jt) {
            const int jc = jb * BN + jt * 8 + 2 * tg;
            float p00 = (jc     <= gi0) ? __expf(sacc[jt][0]) : 0.f;
            float p01 = (jc + 1 <= gi0) ? __expf(sacc[jt][1]) : 0.f;
            float p10 = (jc     <= gi1) ? __expf(sacc[jt][2]) : 0.f;
            float p11 = (jc + 1 <= gi1) ? __expf(sacc[jt][3]) : 0.f;
            ls0 += p00 + p01;
            ls1 += p10 + p11;
            pvA[jt] = packh2(p00, p01);
            pvB[jt] = packh2(p10, p11);
        }

        // ---- GEMM2: O[16i x 128d] += P[16i x 64j] * V[64j x 128d] ----
        const uint32_t vtb = svc + rowA * 256;
        #pragma unroll
        for (int kt = 0; kt < 4; ++kt) {
            uint32_t bV[8][4];
            #pragma unroll
            for (int dp = 0; dp < 8; ++dp)
                ldsm4t(bV[dp], vtb + (uint32_t)kt * 4096 + remVT[dp]);
            const uint32_t a0 = pvA[2 * kt],     a1 = pvB[2 * kt];
            const uint32_t a2 = pvA[2 * kt + 1], a3 = pvB[2 * kt + 1];
            #pragma unroll
            for (int dg = 0; dg < 16; ++dg)
                mma16(oacc[dg], a0, a1, a2, a3,
                      bV[dg >> 1][(dg & 1) * 2], bV[dg >> 1][(dg & 1) * 2 + 1]);
        }

        cpasync_wait0();
        __syncthreads();   // next V landed; all reads of V[cur] done
    }

    // ---- epilogue: lsum reduce within quad (rows complete in-warp) ----
    ls0 += __shfl_xor_sync(0xffffffffu, ls0, 1);
    ls0 += __shfl_xor_sync(0xffffffffu, ls0, 2);
    ls1 += __shfl_xor_sync(0xffffffffu, ls1, 1);
    ls1 += __shfl_xor_sync(0xffffffffu, ls1, 2);
    const float inv0 = 1.f / ls0;
    const float inv1 = 1.f / ls1;

    float* o0 = Oh + (size_t)gi0 * D + 2 * tg;
    float* o1 = Oh + (size_t)gi1 * D + 2 * tg;
    #pragma unroll
    for (int dg = 0; dg < 16; ++dg) {
        float2 w0 = make_float2(oacc[dg][0] * inv0, oacc[dg][1] * inv0);
        float2 w1 = make_float2(oacc[dg][2] * inv1, oacc[dg][3] * inv1);
        *reinterpret_cast<float2*>(o0 + dg * 8) = w0;
        *reinterpret_cast<float2*>(o1 + dg * 8) = w1;
    }
}

}  // namespace

extern "C" void kernel_launch(void* const* d_in, const int* /*in_sizes*/, int /*n_in*/,
                              void* d_out, int /*out_size*/) {
    // inputs: d_in[0]=q (unused by reference), d_in[1]=k, d_in[2]=v
    const float* k = reinterpret_cast<const float*>(d_in[1]);
    const float* v = reinterpret_cast<const float*>(d_in[2]);
    float* o = reinterpret_cast<float*>(d_out);

    cvt16<<<(unsigned)(NELEM / 4 / 256), 256>>>(k, v);

    cudaFuncSetAttribute(fa_regP,
                         cudaFuncAttributeMaxDynamicSharedMemorySize, SMEM_BYTES);
    dim3 grid(S / BM, 32);
    fa_regP<<<grid, NTHREADS, SMEM_BYTES>>>(o);
}